// round 3
// baseline (speedup 1.0000x reference)
#include <cuda_runtime.h>
#include <math.h>

#define BB 256
#define SS 6
#define CC 80
#define FF 2048
#define EE 300
#define HH 1024
#define PP 196

// output layout (float offsets)
#define OUT_OUTPUT 0              // [256*80]
#define OUT_PROBS  20480          // [256*6]
#define OUT_SEN    22016          // [1]
#define OUT_BEN    22017          // [1]
#define OUT_COMATS 22018          // [256*80*80]

// scratch (device globals — no allocation allowed)
__device__ float d_img[BB*FF];
__device__ int   d_ids[BB];
__device__ float d_cp[SS*CC*CC];    // comat2prob per scene
__device__ float d_adj[SS*CC*CC];   // per-scene adjacency
__device__ float d_X0[CC*HH];       // inp @ W1
__device__ float d_hs[SS*CC*HH];    // leakyrelu(adj_s @ X0)
__device__ float d_v[BB*HH];        // img_feats @ W2^T

// ---------------- K1: global max-pool over 14x14 (float4) ----------------
__global__ void k_maxpool(const float4* __restrict__ x4) {
    int gw = (blockIdx.x * blockDim.x + threadIdx.x) >> 5;   // one warp per (b,f) row
    int lane = threadIdx.x & 31;
    if (gw >= BB * FF) return;
    const float4* p = x4 + (size_t)gw * 49;                  // 196 = 49 * float4
    float4 a = p[lane];
    float m = fmaxf(fmaxf(a.x, a.y), fmaxf(a.z, a.w));
    if (lane < 17) {
        float4 b = p[32 + lane];
        m = fmaxf(m, fmaxf(fmaxf(b.x, b.y), fmaxf(b.z, b.w)));
    }
    #pragma unroll
    for (int o = 16; o; o >>= 1) m = fmaxf(m, __shfl_xor_sync(0xffffffffu, m, o));
    if (lane == 0) d_img[gw] = m;
}

// ------------- K2: scene scores + softmax + argmax -------------
__global__ void k_scene(const float* __restrict__ Wsc, float* __restrict__ out) {
    int b = blockIdx.x;
    int tid = threadIdx.x;
    __shared__ float sh[6][256];
    float acc[6] = {0.f,0.f,0.f,0.f,0.f,0.f};
    const float* row = d_img + b * FF;
    for (int f = tid; f < FF; f += 256) {
        float xv = row[f];
        const float* w = Wsc + f * SS;
        #pragma unroll
        for (int s = 0; s < 6; s++) acc[s] = fmaf(xv, w[s], acc[s]);
    }
    #pragma unroll
    for (int s = 0; s < 6; s++) sh[s][tid] = acc[s];
    __syncthreads();
    for (int st = 128; st > 0; st >>= 1) {
        if (tid < st) {
            #pragma unroll
            for (int s = 0; s < 6; s++) sh[s][tid] += sh[s][tid + st];
        }
        __syncthreads();
    }
    if (tid == 0) {
        float sc[6]; float m = -3.4e38f; int am = 0;
        #pragma unroll
        for (int s = 0; s < 6; s++) {
            sc[s] = sh[s][0];
            if (sc[s] > m) { m = sc[s]; am = s; }
        }
        float e[6], sum = 0.f;
        #pragma unroll
        for (int s = 0; s < 6; s++) { e[s] = expf(sc[s] - m); sum += e[s]; }
        float inv = 1.0f / sum;
        #pragma unroll
        for (int s = 0; s < 6; s++) out[OUT_PROBS + b * 6 + s] = e[s] * inv;
        d_ids[b] = am;
    }
}

// ------------- K3: comatrix update + comat2prob + gen_adj (fused, 1 block/scene) -------------
__global__ void k_comat_adj(const float* __restrict__ y, const float* __restrict__ com_in) {
    int s = blockIdx.x;
    int tid = threadIdx.x;
    __shared__ float yS[64][CC];      // 20480 B
    __shared__ float cmS[CC * CC];    // 25600 B
    __shared__ float dgS[CC];
    __shared__ float DvS[CC];
    __shared__ int list[BB];
    __shared__ int cnt;

    // deterministic per-scene batch list (thread 0 serial scan)
    if (tid == 0) {
        int c = 0;
        for (int b = 0; b < BB; b++)
            if (d_ids[b] == s) list[c++] = b;
        cnt = c;
    }
    __syncthreads();
    int n = cnt;

    // 5x5 register accumulators; thread (ti,tj): rows ti*5.., cols tj*5..
    int ti = tid >> 4, tj = tid & 15;
    int i0 = ti * 5, j0 = tj * 5;
    float acc[5][5];
    #pragma unroll
    for (int a = 0; a < 5; a++)
        #pragma unroll
        for (int b = 0; b < 5; b++) acc[a][b] = 0.f;

    for (int t0 = 0; t0 < n; t0 += 64) {
        int nt = min(64, n - t0);
        // load tile of selected y rows, coalesced
        for (int l = tid; l < 64 * CC; l += 256) {
            int r = l / CC, c = l - r * CC;
            yS[r][c] = (r < nt) ? y[list[t0 + r] * CC + c] : 0.f;
        }
        __syncthreads();
        for (int r = 0; r < nt; r++) {
            float yi[5], yj[5];
            #pragma unroll
            for (int a = 0; a < 5; a++) yi[a] = yS[r][i0 + a];
            #pragma unroll
            for (int b = 0; b < 5; b++) yj[b] = yS[r][j0 + b];
            #pragma unroll
            for (int a = 0; a < 5; a++)
                #pragma unroll
                for (int b = 0; b < 5; b++)
                    acc[a][b] = fmaf(yi[a], yj[b], acc[a][b]);
        }
        __syncthreads();
    }

    // cm = com_in + acc  (into smem)
    #pragma unroll
    for (int a = 0; a < 5; a++)
        #pragma unroll
        for (int b = 0; b < 5; b++) {
            int idx = (i0 + a) * CC + (j0 + b);
            cmS[idx] = com_in[s * CC * CC + idx] + acc[a][b];
        }
    __syncthreads();
    // diagonal
    for (int i = tid; i < CC; i += 256) dgS[i] = cmS[i * CC + i];
    __syncthreads();
    // comat2prob in place + write d_cp
    for (int idx = tid; idx < CC * CC; idx += 256) {
        int i = idx / CC, j = idx - i * CC;
        float vv = (i == j) ? 1.0f : cmS[idx] / (dgS[i] + 1e-8f);
        cmS[idx] = vv;
        d_cp[s * CC * CC + idx] = vv;
    }
    __syncthreads();
    // row sums -> D^{-1/2}
    for (int i = tid; i < CC; i += 256) {
        float sm = 0.f;
        for (int j = 0; j < CC; j++) sm += cmS[i * CC + j];
        DvS[i] = rsqrtf(sm);
    }
    __syncthreads();
    // adj = Dv[i] * cp^T * Dv[j]
    for (int idx = tid; idx < CC * CC; idx += 256) {
        int i = idx / CC, j = idx - i * CC;
        d_adj[s * CC * CC + idx] = DvS[i] * cmS[j * CC + i] * DvS[j];
    }
}

// ------------- K4: gather comats to output (+ entropy in last block) -------------
__global__ void k_gather(float* __restrict__ out) {
    if (blockIdx.x == 3200) {
        // entropy terms
        int b = threadIdx.x;
        __shared__ float shE[256];
        __shared__ float shP[6][256];
        float en = 0.f;
        #pragma unroll
        for (int s = 0; s < 6; s++) {
            float p = out[OUT_PROBS + b * 6 + s];
            en -= p * logf(p + 1e-7f);
            shP[s][b] = p;
        }
        shE[b] = en;
        __syncthreads();
        for (int st = 128; st > 0; st >>= 1) {
            if (b < st) {
                shE[b] += shE[b + st];
                #pragma unroll
                for (int s = 0; s < 6; s++) shP[s][b] += shP[s][b + st];
            }
            __syncthreads();
        }
        if (b == 0) {
            out[OUT_SEN] = shE[0] / 256.0f;
            float maxen = -logf(1.0f / 6.0f + 1e-7f);
            float be = 0.f;
            #pragma unroll
            for (int s = 0; s < 6; s++) {
                float mp = shP[s][0] / 256.0f;
                be -= mp * logf(mp + 1e-7f);
            }
            out[OUT_BEN] = (maxen - be) * 100.0f;
        }
        return;
    }
    int idx = blockIdx.x * 256 + threadIdx.x;       // over B * 3200 float2
    int b = idx / (CC * CC / 2);
    int r = idx - b * (CC * CC / 2);
    int s = d_ids[b];
    const float2* src = (const float2*)(d_cp + s * CC * CC);
    ((float2*)(out + OUT_COMATS))[idx] = src[r];
}

// ------------- K5: X0 = inp @ W1  [80,300]x[300,1024] -------------
__global__ void k_x0(const float* __restrict__ inp, const float* __restrict__ W1) {
    __shared__ float inpS[16][EE];
    int tid = threadIdx.x;
    int cg = blockIdx.x, rg = blockIdx.y;
    for (int l = tid; l < 16 * EE; l += 256) {
        int r = l / EE, c = l - r * EE;
        inpS[r][c] = inp[(rg * 16 + r) * EE + c];
    }
    __syncthreads();
    int col = cg * 128 + (tid & 127);
    int half = tid >> 7;
    float acc[8] = {};
    for (int k = 0; k < EE; k++) {
        float w = W1[k * HH + col];
        #pragma unroll
        for (int rr = 0; rr < 8; rr++)
            acc[rr] = fmaf(inpS[half + 2 * rr][k], w, acc[rr]);
    }
    #pragma unroll
    for (int rr = 0; rr < 8; rr++)
        d_X0[(rg * 16 + half + 2 * rr) * HH + col] = acc[rr];
}

// ------------- K6: v = img_feats @ W2^T  (NT GEMM, M=256,N=1024,K=2048) -------------
__global__ void k_vgemm(const float* __restrict__ W2) {
    __shared__ float As[32][34];   // k-major, padded
    __shared__ float Bs[32][68];   // k-major, padded (16B-aligned rows)
    int tid = threadIdx.x;
    int row0 = blockIdx.y * 32;
    int col0 = blockIdx.x * 64;
    int ty = tid >> 4;   // 0..15 -> 2 rows each
    int tx = tid & 15;   // 0..15 -> 4 cols each
    float acc[2][4] = {};
    const float* Abase = d_img + (size_t)row0 * FF;
    const float* Bbase = W2 + (size_t)col0 * FF;
    for (int k0 = 0; k0 < FF; k0 += 32) {
        int l = tid;
        #pragma unroll
        for (int it = 0; it < 4; it++) {   // 32x32 A tile
            int r = l >> 5, c = l & 31;
            As[c][r] = Abase[r * FF + k0 + c];
            l += 256;
        }
        l = tid;
        #pragma unroll
        for (int it = 0; it < 8; it++) {   // 64x32 B tile
            int r = l >> 5, c = l & 31;
            Bs[c][r] = Bbase[r * FF + k0 + c];
            l += 256;
        }
        __syncthreads();
        #pragma unroll
        for (int kk = 0; kk < 32; kk++) {
            float2 a = *(const float2*)&As[kk][ty * 2];
            float4 bb = *(const float4*)&Bs[kk][tx * 4];
            acc[0][0] = fmaf(a.x, bb.x, acc[0][0]);
            acc[0][1] = fmaf(a.x, bb.y, acc[0][1]);
            acc[0][2] = fmaf(a.x, bb.z, acc[0][2]);
            acc[0][3] = fmaf(a.x, bb.w, acc[0][3]);
            acc[1][0] = fmaf(a.y, bb.x, acc[1][0]);
            acc[1][1] = fmaf(a.y, bb.y, acc[1][1]);
            acc[1][2] = fmaf(a.y, bb.z, acc[1][2]);
            acc[1][3] = fmaf(a.y, bb.w, acc[1][3]);
        }
        __syncthreads();
    }
    #pragma unroll
    for (int i = 0; i < 2; i++) {
        int r = row0 + ty * 2 + i;
        #pragma unroll
        for (int j = 0; j < 4; j++)
            d_v[r * HH + col0 + tx * 4 + j] = acc[i][j];
    }
}

// ------------- K7: h_s = leakyrelu(adj_s @ X0) (6 scenes) -------------
__global__ void k_h() {
    int s = blockIdx.x;   // 0..5
    int g = blockIdx.y;   // 0..15  (cols g*64 .. g*64+63)
    __shared__ float adjS[CC * CC];   // 25.6 KB
    __shared__ float xS[CC][64];      // 20.5 KB
    int tid = threadIdx.x;
    for (int i = tid; i < CC * CC; i += 256) adjS[i] = d_adj[s * CC * CC + i];
    for (int i = tid; i < CC * 64; i += 256) {
        int r = i >> 6, c = i & 63;
        xS[r][c] = d_X0[r * HH + g * 64 + c];
    }
    __syncthreads();
    int col = tid & 63;
    int r0 = tid >> 6;   // 0..3
    float acc[20];
    #pragma unroll
    for (int a = 0; a < 20; a++) acc[a] = 0.f;
    for (int k = 0; k < CC; k++) {
        float xv = xS[k][col];
        #pragma unroll
        for (int a = 0; a < 20; a++)
            acc[a] = fmaf(adjS[(r0 + 4 * a) * CC + k], xv, acc[a]);
    }
    #pragma unroll
    for (int a = 0; a < 20; a++) {
        int row = r0 + 4 * a;
        float hv = acc[a];
        hv = hv > 0.f ? hv : 0.2f * hv;
        d_hs[(s * CC + row) * HH + g * 64 + col] = hv;
    }
}

// ------------- K8: g = h_s · v[b];  output[b] = adj_s @ g -------------
__global__ void k_out(float* __restrict__ out) {
    int b = blockIdx.x;
    int tid = threadIdx.x;
    int lane = tid & 31, w = tid >> 5;
    __shared__ float vb[HH];
    __shared__ float g[CC];
    int s = d_ids[b];
    // vectorized copy of v[b] into smem
    ((float4*)vb)[tid] = ((const float4*)(d_v + (size_t)b * HH))[tid];
    __syncthreads();
    const float4* vb4 = (const float4*)vb;
    for (int j = w; j < CC; j += 8) {
        const float4* hr4 = (const float4*)(d_hs + (size_t)(s * CC + j) * HH);
        float acc = 0.f;
        #pragma unroll
        for (int k = 0; k < 8; k++) {
            float4 hv = hr4[lane + k * 32];
            float4 vv = vb4[lane + k * 32];
            acc = fmaf(hv.x, vv.x, acc);
            acc = fmaf(hv.y, vv.y, acc);
            acc = fmaf(hv.z, vv.z, acc);
            acc = fmaf(hv.w, vv.w, acc);
        }
        #pragma unroll
        for (int o = 16; o; o >>= 1) acc += __shfl_xor_sync(0xffffffffu, acc, o);
        if (lane == 0) g[j] = acc;
    }
    __syncthreads();
    if (tid < CC) {
        const float* ar = d_adj + s * CC * CC + tid * CC;
        float acc = 0.f;
        #pragma unroll 8
        for (int j = 0; j < CC; j++) acc = fmaf(ar[j], g[j], acc);
        out[OUT_OUTPUT + b * CC + tid] = acc;
    }
}

extern "C" void kernel_launch(void* const* d_in, const int* in_sizes, int n_in,
                              void* d_out, int out_size) {
    const float* x    = (const float*)d_in[0];
    const float* inp  = (const float*)d_in[1];
    const float* y    = (const float*)d_in[2];
    const float* com  = (const float*)d_in[3];
    const float* Wsc  = (const float*)d_in[4];
    const float* W1   = (const float*)d_in[5];
    const float* W2   = (const float*)d_in[6];
    float* out = (float*)d_out;

    k_maxpool<<<(BB * FF) / 8, 256>>>((const float4*)x);  // 1: d_img
    k_x0<<<dim3(8, 5), 256>>>(inp, W1);                   // 2: d_X0
    k_scene<<<BB, 256>>>(Wsc, out);                       // 3: probs + ids
    k_comat_adj<<<SS, 256>>>(y, com);                     // 4: d_cp, d_adj
    k_gather<<<3201, 256>>>(out);                         // 5: comats out + entropy
    k_vgemm<<<dim3(16, 8), 256>>>(W2);                    // 6: d_v
    k_h<<<dim3(6, 16), 256>>>();                          // 7: d_hs
    k_out<<<BB, 256>>>(out);                              // 8: output
}

// round 6
// speedup vs baseline: 1.3728x; 1.3728x over previous
#include <cuda_runtime.h>
#include <math.h>

#define BB 256
#define SS 6
#define CC 80
#define FF 2048
#define EE 300
#define HH 1024
#define PP 196

// output layout (float offsets)
#define OUT_OUTPUT 0              // [256*80]
#define OUT_PROBS  20480          // [256*6]
#define OUT_SEN    22016          // [1]
#define OUT_BEN    22017          // [1]
#define OUT_COMATS 22018          // [256*80*80]

// scratch (device globals — no allocation allowed)
__device__ float d_img[BB*FF];
__device__ int   d_ids[BB];
__device__ float d_cp[SS*CC*CC];    // comat2prob per scene
__device__ float d_adj[SS*CC*CC];   // per-scene adjacency
__device__ float d_X0[CC*HH];       // inp @ W1
__device__ float d_hs[SS*CC*HH];    // leakyrelu(adj_s @ X0)
__device__ float d_v[BB*HH];        // img_feats @ W2^T

// host-side stream/event resources (no device memory)
static cudaStream_t g_s2;
static cudaEvent_t g_evImg, g_evX0, g_evV, g_evAdj, g_evG;
struct GInit {
    GInit() {
        cudaStreamCreateWithFlags(&g_s2, cudaStreamNonBlocking);
        cudaEventCreateWithFlags(&g_evImg, cudaEventDisableTiming);
        cudaEventCreateWithFlags(&g_evX0,  cudaEventDisableTiming);
        cudaEventCreateWithFlags(&g_evV,   cudaEventDisableTiming);
        cudaEventCreateWithFlags(&g_evAdj, cudaEventDisableTiming);
        cudaEventCreateWithFlags(&g_evG,   cudaEventDisableTiming);
    }
};
static GInit g_init;

// ---------------- K1: global max-pool over 14x14 (float4) ----------------
__global__ void k_maxpool(const float4* __restrict__ x4) {
    int gw = (blockIdx.x * blockDim.x + threadIdx.x) >> 5;   // one warp per (b,f) row
    int lane = threadIdx.x & 31;
    if (gw >= BB * FF) return;
    const float4* p = x4 + (size_t)gw * 49;                  // 196 = 49 * float4
    float4 a = p[lane];
    float m = fmaxf(fmaxf(a.x, a.y), fmaxf(a.z, a.w));
    if (lane < 17) {
        float4 b = p[32 + lane];
        m = fmaxf(m, fmaxf(fmaxf(b.x, b.y), fmaxf(b.z, b.w)));
    }
    #pragma unroll
    for (int o = 16; o; o >>= 1) m = fmaxf(m, __shfl_xor_sync(0xffffffffu, m, o));
    if (lane == 0) d_img[gw] = m;
}

// ------------- K2: scene scores + softmax + argmax -------------
__global__ void k_scene(const float* __restrict__ Wsc, float* __restrict__ out) {
    int b = blockIdx.x;
    int tid = threadIdx.x;
    __shared__ float sh[6][256];
    float acc[6] = {0.f,0.f,0.f,0.f,0.f,0.f};
    const float* row = d_img + b * FF;
    for (int f = tid; f < FF; f += 256) {
        float xv = row[f];
        const float* w = Wsc + f * SS;
        #pragma unroll
        for (int s = 0; s < 6; s++) acc[s] = fmaf(xv, w[s], acc[s]);
    }
    #pragma unroll
    for (int s = 0; s < 6; s++) sh[s][tid] = acc[s];
    __syncthreads();
    for (int st = 128; st > 0; st >>= 1) {
        if (tid < st) {
            #pragma unroll
            for (int s = 0; s < 6; s++) sh[s][tid] += sh[s][tid + st];
        }
        __syncthreads();
    }
    if (tid == 0) {
        float sc[6]; float m = -3.4e38f; int am = 0;
        #pragma unroll
        for (int s = 0; s < 6; s++) {
            sc[s] = sh[s][0];
            if (sc[s] > m) { m = sc[s]; am = s; }
        }
        float e[6], sum = 0.f;
        #pragma unroll
        for (int s = 0; s < 6; s++) { e[s] = expf(sc[s] - m); sum += e[s]; }
        float inv = 1.0f / sum;
        #pragma unroll
        for (int s = 0; s < 6; s++) out[OUT_PROBS + b * 6 + s] = e[s] * inv;
        d_ids[b] = am;
    }
}

// ------------- K3: comatrix update + comat2prob + gen_adj (fused, 1 block/scene) -------------
__global__ void k_comat_adj(const float* __restrict__ y, const float* __restrict__ com_in) {
    int s = blockIdx.x;
    int tid = threadIdx.x;
    __shared__ float yS[64][CC];      // 20480 B
    __shared__ float cmS[CC * CC];    // 25600 B
    __shared__ float dgS[CC];
    __shared__ float DvS[CC];
    __shared__ int sid[BB];
    __shared__ int list[BB];
    __shared__ int cnt;

    // cooperative ids load (1 coalesced round-trip), then cheap smem scan
    sid[tid] = d_ids[tid];
    __syncthreads();
    if (tid == 0) {
        int c = 0;
        #pragma unroll 8
        for (int b = 0; b < BB; b++)
            if (sid[b] == s) list[c++] = b;
        cnt = c;
    }
    __syncthreads();
    int n = cnt;

    // 5x5 register accumulators; thread (ti,tj): rows ti*5.., cols tj*5..
    int ti = tid >> 4, tj = tid & 15;
    int i0 = ti * 5, j0 = tj * 5;
    float acc[5][5];
    #pragma unroll
    for (int a = 0; a < 5; a++)
        #pragma unroll
        for (int b = 0; b < 5; b++) acc[a][b] = 0.f;

    for (int t0 = 0; t0 < n; t0 += 64) {
        int nt = min(64, n - t0);
        // load tile of selected y rows, coalesced
        for (int l = tid; l < 64 * CC; l += 256) {
            int r = l / CC, c = l - r * CC;
            yS[r][c] = (r < nt) ? y[list[t0 + r] * CC + c] : 0.f;
        }
        __syncthreads();
        for (int r = 0; r < nt; r++) {
            float yi[5], yj[5];
            #pragma unroll
            for (int a = 0; a < 5; a++) yi[a] = yS[r][i0 + a];
            #pragma unroll
            for (int b = 0; b < 5; b++) yj[b] = yS[r][j0 + b];
            #pragma unroll
            for (int a = 0; a < 5; a++)
                #pragma unroll
                for (int b = 0; b < 5; b++)
                    acc[a][b] = fmaf(yi[a], yj[b], acc[a][b]);
        }
        __syncthreads();
    }

    // cm = com_in + acc  (into smem)
    #pragma unroll
    for (int a = 0; a < 5; a++)
        #pragma unroll
        for (int b = 0; b < 5; b++) {
            int idx = (i0 + a) * CC + (j0 + b);
            cmS[idx] = com_in[s * CC * CC + idx] + acc[a][b];
        }
    __syncthreads();
    // diagonal
    for (int i = tid; i < CC; i += 256) dgS[i] = cmS[i * CC + i];
    __syncthreads();
    // comat2prob in place + write d_cp
    for (int idx = tid; idx < CC * CC; idx += 256) {
        int i = idx / CC, j = idx - i * CC;
        float vv = (i == j) ? 1.0f : cmS[idx] / (dgS[i] + 1e-8f);
        cmS[idx] = vv;
        d_cp[s * CC * CC + idx] = vv;
    }
    __syncthreads();
    // row sums -> D^{-1/2}
    for (int i = tid; i < CC; i += 256) {
        float sm = 0.f;
        #pragma unroll 8
        for (int j = 0; j < CC; j++) sm += cmS[i * CC + j];
        DvS[i] = rsqrtf(sm);
    }
    __syncthreads();
    // adj = Dv[i] * cp^T * Dv[j]
    for (int idx = tid; idx < CC * CC; idx += 256) {
        int i = idx / CC, j = idx - i * CC;
        d_adj[s * CC * CC + idx] = DvS[i] * cmS[j * CC + i] * DvS[j];
    }
}

// ------------- K4: gather comats to output (+ entropy in last block) -------------
__global__ void k_gather(float* __restrict__ out) {
    if (blockIdx.x == 3200) {
        // entropy terms
        int b = threadIdx.x;
        __shared__ float shE[256];
        __shared__ float shP[6][256];
        float en = 0.f;
        #pragma unroll
        for (int s = 0; s < 6; s++) {
            float p = out[OUT_PROBS + b * 6 + s];
            en -= p * logf(p + 1e-7f);
            shP[s][b] = p;
        }
        shE[b] = en;
        __syncthreads();
        for (int st = 128; st > 0; st >>= 1) {
            if (b < st) {
                shE[b] += shE[b + st];
                #pragma unroll
                for (int s = 0; s < 6; s++) shP[s][b] += shP[s][b + st];
            }
            __syncthreads();
        }
        if (b == 0) {
            out[OUT_SEN] = shE[0] / 256.0f;
            float maxen = -logf(1.0f / 6.0f + 1e-7f);
            float be = 0.f;
            #pragma unroll
            for (int s = 0; s < 6; s++) {
                float mp = shP[s][0] / 256.0f;
                be -= mp * logf(mp + 1e-7f);
            }
            out[OUT_BEN] = (maxen - be) * 100.0f;
        }
        return;
    }
    int idx = blockIdx.x * 256 + threadIdx.x;       // over B * 3200 float2
    int b = idx / (CC * CC / 2);
    int r = idx - b * (CC * CC / 2);
    int s = d_ids[b];
    const float2* src = (const float2*)(d_cp + s * CC * CC);
    ((float2*)(out + OUT_COMATS))[idx] = src[r];
}

// ------------- K5: X0 = inp @ W1  [80,300]x[300,1024] -------------
__global__ void k_x0(const float* __restrict__ inp, const float* __restrict__ W1) {
    __shared__ float inpS[16][EE];
    int tid = threadIdx.x;
    int cg = blockIdx.x, rg = blockIdx.y;
    for (int l = tid; l < 16 * EE; l += 256) {
        int r = l / EE, c = l - r * EE;
        inpS[r][c] = inp[(rg * 16 + r) * EE + c];
    }
    __syncthreads();
    int col = cg * 128 + (tid & 127);
    int half = tid >> 7;
    float acc[8] = {};
    for (int k = 0; k < EE; k++) {
        float w = W1[k * HH + col];
        #pragma unroll
        for (int rr = 0; rr < 8; rr++)
            acc[rr] = fmaf(inpS[half + 2 * rr][k], w, acc[rr]);
    }
    #pragma unroll
    for (int rr = 0; rr < 8; rr++)
        d_X0[(rg * 16 + half + 2 * rr) * HH + col] = acc[rr];
}

// ------------- K6: v = img_feats @ W2^T  (NT GEMM, M=256,N=1024,K=2048) -------------
__global__ void k_vgemm(const float* __restrict__ W2) {
    __shared__ float As[32][34];   // k-major, padded
    __shared__ float Bs[32][68];   // k-major, padded (16B-aligned rows)
    int tid = threadIdx.x;
    int row0 = blockIdx.y * 32;
    int col0 = blockIdx.x * 64;
    int ty = tid >> 4;   // 0..15 -> 2 rows each
    int tx = tid & 15;   // 0..15 -> 4 cols each
    float acc[2][4] = {};
    const float* Abase = d_img + (size_t)row0 * FF;
    const float* Bbase = W2 + (size_t)col0 * FF;
    for (int k0 = 0; k0 < FF; k0 += 32) {
        int l = tid;
        #pragma unroll
        for (int it = 0; it < 4; it++) {   // 32x32 A tile
            int r = l >> 5, c = l & 31;
            As[c][r] = Abase[r * FF + k0 + c];
            l += 256;
        }
        l = tid;
        #pragma unroll
        for (int it = 0; it < 8; it++) {   // 64x32 B tile
            int r = l >> 5, c = l & 31;
            Bs[c][r] = Bbase[r * FF + k0 + c];
            l += 256;
        }
        __syncthreads();
        #pragma unroll
        for (int kk = 0; kk < 32; kk++) {
            float2 a = *(const float2*)&As[kk][ty * 2];
            float4 bb = *(const float4*)&Bs[kk][tx * 4];
            acc[0][0] = fmaf(a.x, bb.x, acc[0][0]);
            acc[0][1] = fmaf(a.x, bb.y, acc[0][1]);
            acc[0][2] = fmaf(a.x, bb.z, acc[0][2]);
            acc[0][3] = fmaf(a.x, bb.w, acc[0][3]);
            acc[1][0] = fmaf(a.y, bb.x, acc[1][0]);
            acc[1][1] = fmaf(a.y, bb.y, acc[1][1]);
            acc[1][2] = fmaf(a.y, bb.z, acc[1][2]);
            acc[1][3] = fmaf(a.y, bb.w, acc[1][3]);
        }
        __syncthreads();
    }
    #pragma unroll
    for (int i = 0; i < 2; i++) {
        int r = row0 + ty * 2 + i;
        #pragma unroll
        for (int j = 0; j < 4; j++)
            d_v[r * HH + col0 + tx * 4 + j] = acc[i][j];
    }
}

// ------------- K7: h_s = leakyrelu(adj_s @ X0) (6 scenes) -------------
__global__ void k_h() {
    int s = blockIdx.x;   // 0..5
    int g = blockIdx.y;   // 0..15  (cols g*64 .. g*64+63)
    __shared__ float adjS[CC * CC];   // 25.6 KB
    __shared__ float xS[CC][64];      // 20.5 KB
    int tid = threadIdx.x;
    for (int i = tid; i < CC * CC; i += 256) adjS[i] = d_adj[s * CC * CC + i];
    for (int i = tid; i < CC * 64; i += 256) {
        int r = i >> 6, c = i & 63;
        xS[r][c] = d_X0[r * HH + g * 64 + c];
    }
    __syncthreads();
    int col = tid & 63;
    int r0 = tid >> 6;   // 0..3
    float acc[20];
    #pragma unroll
    for (int a = 0; a < 20; a++) acc[a] = 0.f;
    for (int k = 0; k < CC; k++) {
        float xv = xS[k][col];
        #pragma unroll
        for (int a = 0; a < 20; a++)
            acc[a] = fmaf(adjS[(r0 + 4 * a) * CC + k], xv, acc[a]);
    }
    #pragma unroll
    for (int a = 0; a < 20; a++) {
        int row = r0 + 4 * a;
        float hv = acc[a];
        hv = hv > 0.f ? hv : 0.2f * hv;
        d_hs[(s * CC + row) * HH + g * 64 + col] = hv;
    }
}

// ------------- K8: g = h_s · v[b];  output[b] = adj_s @ g -------------
__global__ void k_out(float* __restrict__ out) {
    int b = blockIdx.x;
    int tid = threadIdx.x;
    int lane = tid & 31, w = tid >> 5;
    __shared__ float vb[HH];
    __shared__ float g[CC];
    int s = d_ids[b];
    // vectorized copy of v[b] into smem
    ((float4*)vb)[tid] = ((const float4*)(d_v + (size_t)b * HH))[tid];
    __syncthreads();
    const float4* vb4 = (const float4*)vb;
    for (int j = w; j < CC; j += 8) {
        const float4* hr4 = (const float4*)(d_hs + (size_t)(s * CC + j) * HH);
        float acc = 0.f;
        #pragma unroll
        for (int k = 0; k < 8; k++) {
            float4 hv = hr4[lane + k * 32];
            float4 vv = vb4[lane + k * 32];
            acc = fmaf(hv.x, vv.x, acc);
            acc = fmaf(hv.y, vv.y, acc);
            acc = fmaf(hv.z, vv.z, acc);
            acc = fmaf(hv.w, vv.w, acc);
        }
        #pragma unroll
        for (int o = 16; o; o >>= 1) acc += __shfl_xor_sync(0xffffffffu, acc, o);
        if (lane == 0) g[j] = acc;
    }
    __syncthreads();
    if (tid < CC) {
        const float* ar = d_adj + s * CC * CC + tid * CC;
        float acc = 0.f;
        #pragma unroll 8
        for (int j = 0; j < CC; j++) acc = fmaf(ar[j], g[j], acc);
        out[OUT_OUTPUT + b * CC + tid] = acc;
    }
}

extern "C" void kernel_launch(void* const* d_in, const int* in_sizes, int n_in,
                              void* d_out, int out_size) {
    const float* x    = (const float*)d_in[0];
    const float* inp  = (const float*)d_in[1];
    const float* y    = (const float*)d_in[2];
    const float* com  = (const float*)d_in[3];
    const float* Wsc  = (const float*)d_in[4];
    const float* W1   = (const float*)d_in[5];
    const float* W2   = (const float*)d_in[6];
    float* out = (float*)d_out;

    // ---- main stream (capture origin) ----
    k_maxpool<<<(BB * FF) / 8, 256>>>((const float4*)x);
    cudaEventRecord(g_evImg, 0);                 // fork point (recorded in capture stream)

    // ---- side stream: joins capture via wait on evImg FIRST ----
    cudaStreamWaitEvent(g_s2, g_evImg, 0);
    k_x0<<<dim3(8, 5), 256, 0, g_s2>>>(inp, W1);
    cudaEventRecord(g_evX0, g_s2);
    k_vgemm<<<dim3(16, 8), 256, 0, g_s2>>>(W2);
    cudaEventRecord(g_evV, g_s2);

    // ---- main stream continues (overlaps x0+vgemm) ----
    k_scene<<<BB, 256>>>(Wsc, out);
    k_comat_adj<<<SS, 256>>>(y, com);
    cudaEventRecord(g_evAdj, 0);

    // side stream: gather (needs cp/ids/probs) overlaps h/out
    cudaStreamWaitEvent(g_s2, g_evAdj, 0);
    k_gather<<<3201, 256, 0, g_s2>>>(out);
    cudaEventRecord(g_evG, g_s2);

    // main: h needs X0 (side) + adj (main)
    cudaStreamWaitEvent(0, g_evX0, 0);
    k_h<<<dim3(6, 16), 256>>>();

    // main: out needs v (side) + hs/adj/ids (main)
    cudaStreamWaitEvent(0, g_evV, 0);
    k_out<<<BB, 256>>>(out);

    // join side stream before capture ends
    cudaStreamWaitEvent(0, g_evG, 0);
}

// round 9
// speedup vs baseline: 1.5567x; 1.1340x over previous
#include <cuda_runtime.h>
#include <math.h>

#define BB 256
#define SS 6
#define CC 80
#define FF 2048
#define EE 300
#define HH 1024
#define PP 196

// output layout (float offsets)
#define OUT_OUTPUT 0              // [256*80]
#define OUT_PROBS  20480          // [256*6]
#define OUT_SEN    22016          // [1]
#define OUT_BEN    22017          // [1]
#define OUT_COMATS 22018          // [256*80*80]

// scratch (device globals — no allocation allowed)
__device__ float d_img[BB*FF];
__device__ int   d_ids[BB];
__device__ float d_cp[SS*CC*CC];    // comat2prob per scene
__device__ float d_adj[SS*CC*CC];   // per-scene adjacency
__device__ float d_X0[CC*HH];       // inp @ W1
__device__ float d_hs[SS*CC*HH];    // leakyrelu(adj_s @ X0)
__device__ float d_v[BB*HH];        // img_feats @ W2^T

// host-side stream/event resources (no device memory)
static cudaStream_t g_s2;
static cudaEvent_t g_evStart, g_evImg, g_evX0, g_evV, g_evAdj, g_evG;
struct GInit {
    GInit() {
        cudaStreamCreateWithFlags(&g_s2, cudaStreamNonBlocking);
        cudaEventCreateWithFlags(&g_evStart, cudaEventDisableTiming);
        cudaEventCreateWithFlags(&g_evImg, cudaEventDisableTiming);
        cudaEventCreateWithFlags(&g_evX0,  cudaEventDisableTiming);
        cudaEventCreateWithFlags(&g_evV,   cudaEventDisableTiming);
        cudaEventCreateWithFlags(&g_evAdj, cudaEventDisableTiming);
        cudaEventCreateWithFlags(&g_evG,   cudaEventDisableTiming);
    }
};
static GInit g_init;

// ---------------- K1: global max-pool over 14x14 (float4) ----------------
__global__ void k_maxpool(const float4* __restrict__ x4) {
    int gw = (blockIdx.x * blockDim.x + threadIdx.x) >> 5;   // one warp per (b,f) row
    int lane = threadIdx.x & 31;
    if (gw >= BB * FF) return;
    const float4* p = x4 + (size_t)gw * 49;                  // 196 = 49 * float4
    float4 a = p[lane];
    float m = fmaxf(fmaxf(a.x, a.y), fmaxf(a.z, a.w));
    if (lane < 17) {
        float4 b = p[32 + lane];
        m = fmaxf(m, fmaxf(fmaxf(b.x, b.y), fmaxf(b.z, b.w)));
    }
    #pragma unroll
    for (int o = 16; o; o >>= 1) m = fmaxf(m, __shfl_xor_sync(0xffffffffu, m, o));
    if (lane == 0) d_img[gw] = m;
}

// ------------- K2: scene scores + softmax + argmax -------------
__global__ void k_scene(const float* __restrict__ Wsc, float* __restrict__ out) {
    int b = blockIdx.x;
    int tid = threadIdx.x;
    __shared__ float sh[6][256];
    float acc[6] = {0.f,0.f,0.f,0.f,0.f,0.f};
    const float* row = d_img + b * FF;
    for (int f = tid; f < FF; f += 256) {
        float xv = row[f];
        const float* w = Wsc + f * SS;
        #pragma unroll
        for (int s = 0; s < 6; s++) acc[s] = fmaf(xv, w[s], acc[s]);
    }
    #pragma unroll
    for (int s = 0; s < 6; s++) sh[s][tid] = acc[s];
    __syncthreads();
    for (int st = 128; st > 0; st >>= 1) {
        if (tid < st) {
            #pragma unroll
            for (int s = 0; s < 6; s++) sh[s][tid] += sh[s][tid + st];
        }
        __syncthreads();
    }
    if (tid == 0) {
        float sc[6]; float m = -3.4e38f; int am = 0;
        #pragma unroll
        for (int s = 0; s < 6; s++) {
            sc[s] = sh[s][0];
            if (sc[s] > m) { m = sc[s]; am = s; }
        }
        float e[6], sum = 0.f;
        #pragma unroll
        for (int s = 0; s < 6; s++) { e[s] = expf(sc[s] - m); sum += e[s]; }
        float inv = 1.0f / sum;
        #pragma unroll
        for (int s = 0; s < 6; s++) out[OUT_PROBS + b * 6 + s] = e[s] * inv;
        d_ids[b] = am;
    }
}

// ------------- K3: comatrix update + comat2prob + gen_adj (fused, 1 block/scene) -------------
__global__ void k_comat_adj(const float* __restrict__ y, const float* __restrict__ com_in) {
    int s = blockIdx.x;
    int tid = threadIdx.x;
    __shared__ float yS[64][CC];      // 20480 B
    __shared__ float cmS[CC * CC];    // 25600 B
    __shared__ float dgS[CC];
    __shared__ float DvS[CC];
    __shared__ int sid[BB];
    __shared__ int list[BB];
    __shared__ int cnt;

    // cooperative ids load (1 coalesced round-trip), then cheap smem scan
    sid[tid] = d_ids[tid];
    __syncthreads();
    if (tid == 0) {
        int c = 0;
        #pragma unroll 8
        for (int b = 0; b < BB; b++)
            if (sid[b] == s) list[c++] = b;
        cnt = c;
    }
    __syncthreads();
    int n = cnt;

    // 5x5 register accumulators; thread (ti,tj): rows ti*5.., cols tj*5..
    int ti = tid >> 4, tj = tid & 15;
    int i0 = ti * 5, j0 = tj * 5;
    float acc[5][5];
    #pragma unroll
    for (int a = 0; a < 5; a++)
        #pragma unroll
        for (int b = 0; b < 5; b++) acc[a][b] = 0.f;

    for (int t0 = 0; t0 < n; t0 += 64) {
        int nt = min(64, n - t0);
        // load tile of selected y rows, coalesced
        for (int l = tid; l < 64 * CC; l += 256) {
            int r = l / CC, c = l - r * CC;
            yS[r][c] = (r < nt) ? y[list[t0 + r] * CC + c] : 0.f;
        }
        __syncthreads();
        for (int r = 0; r < nt; r++) {
            float yi[5], yj[5];
            #pragma unroll
            for (int a = 0; a < 5; a++) yi[a] = yS[r][i0 + a];
            #pragma unroll
            for (int b = 0; b < 5; b++) yj[b] = yS[r][j0 + b];
            #pragma unroll
            for (int a = 0; a < 5; a++)
                #pragma unroll
                for (int b = 0; b < 5; b++)
                    acc[a][b] = fmaf(yi[a], yj[b], acc[a][b]);
        }
        __syncthreads();
    }

    // cm = com_in + acc  (into smem)
    #pragma unroll
    for (int a = 0; a < 5; a++)
        #pragma unroll
        for (int b = 0; b < 5; b++) {
            int idx = (i0 + a) * CC + (j0 + b);
            cmS[idx] = com_in[s * CC * CC + idx] + acc[a][b];
        }
    __syncthreads();
    // diagonal
    for (int i = tid; i < CC; i += 256) dgS[i] = cmS[i * CC + i];
    __syncthreads();
    // comat2prob in place + write d_cp
    for (int idx = tid; idx < CC * CC; idx += 256) {
        int i = idx / CC, j = idx - i * CC;
        float vv = (i == j) ? 1.0f : cmS[idx] / (dgS[i] + 1e-8f);
        cmS[idx] = vv;
        d_cp[s * CC * CC + idx] = vv;
    }
    __syncthreads();
    // row sums -> D^{-1/2}
    for (int i = tid; i < CC; i += 256) {
        float sm = 0.f;
        #pragma unroll 8
        for (int j = 0; j < CC; j++) sm += cmS[i * CC + j];
        DvS[i] = rsqrtf(sm);
    }
    __syncthreads();
    // adj = Dv[i] * cp^T * Dv[j]
    for (int idx = tid; idx < CC * CC; idx += 256) {
        int i = idx / CC, j = idx - i * CC;
        d_adj[s * CC * CC + idx] = DvS[i] * cmS[j * CC + i] * DvS[j];
    }
}

// ------------- K4: gather comats to output (+ entropy in last block) -------------
__global__ void k_gather(float* __restrict__ out) {
    if (blockIdx.x == 3200) {
        // entropy terms
        int b = threadIdx.x;
        __shared__ float shE[256];
        __shared__ float shP[6][256];
        float en = 0.f;
        #pragma unroll
        for (int s = 0; s < 6; s++) {
            float p = out[OUT_PROBS + b * 6 + s];
            en -= p * logf(p + 1e-7f);
            shP[s][b] = p;
        }
        shE[b] = en;
        __syncthreads();
        for (int st = 128; st > 0; st >>= 1) {
            if (b < st) {
                shE[b] += shE[b + st];
                #pragma unroll
                for (int s = 0; s < 6; s++) shP[s][b] += shP[s][b + st];
            }
            __syncthreads();
        }
        if (b == 0) {
            out[OUT_SEN] = shE[0] / 256.0f;
            float maxen = -logf(1.0f / 6.0f + 1e-7f);
            float be = 0.f;
            #pragma unroll
            for (int s = 0; s < 6; s++) {
                float mp = shP[s][0] / 256.0f;
                be -= mp * logf(mp + 1e-7f);
            }
            out[OUT_BEN] = (maxen - be) * 100.0f;
        }
        return;
    }
    int idx = blockIdx.x * 256 + threadIdx.x;       // over B * 3200 float2
    int b = idx / (CC * CC / 2);
    int r = idx - b * (CC * CC / 2);
    int s = d_ids[b];
    const float2* src = (const float2*)(d_cp + s * CC * CC);
    ((float2*)(out + OUT_COMATS))[idx] = src[r];
}

// ------------- K5: X0 = inp @ W1  [80,300]x[300,1024] -------------
__global__ void k_x0(const float* __restrict__ inp, const float* __restrict__ W1) {
    __shared__ float inpS[16][EE];
    int tid = threadIdx.x;
    int cg = blockIdx.x, rg = blockIdx.y;
    for (int l = tid; l < 16 * EE; l += 256) {
        int r = l / EE, c = l - r * EE;
        inpS[r][c] = inp[(rg * 16 + r) * EE + c];
    }
    __syncthreads();
    int col = cg * 128 + (tid & 127);
    int half = tid >> 7;
    float acc[8] = {};
    for (int k = 0; k < EE; k++) {
        float w = W1[k * HH + col];
        #pragma unroll
        for (int rr = 0; rr < 8; rr++)
            acc[rr] = fmaf(inpS[half + 2 * rr][k], w, acc[rr]);
    }
    #pragma unroll
    for (int rr = 0; rr < 8; rr++)
        d_X0[(rg * 16 + half + 2 * rr) * HH + col] = acc[rr];
}

// ------------- K6: v = img_feats @ W2^T  (NT GEMM, M=256,N=1024,K=2048, f32x2) -------------
__global__ void k_vgemm(const float* __restrict__ W2) {
    __shared__ float As[32][34];   // k-major, padded
    __shared__ float Bs[32][68];   // k-major, padded (16B-aligned rows)
    int tid = threadIdx.x;
    int row0 = blockIdx.y * 32;
    int col0 = blockIdx.x * 64;
    int ty = tid >> 4;   // 0..15 -> row pair (2 rows)
    int tx = tid & 15;   // 0..15 -> 4 cols each
    // f32x2 accumulators: [row in pair][col pair] ; bit pattern {0f,0f} == 0ull
    unsigned long long acc00 = 0ull, acc01 = 0ull, acc10 = 0ull, acc11 = 0ull;
    const float* Abase = d_img + (size_t)row0 * FF;
    const float* Bbase = W2 + (size_t)col0 * FF;
    for (int k0 = 0; k0 < FF; k0 += 32) {
        int l = tid;
        #pragma unroll
        for (int it = 0; it < 4; it++) {   // 32x32 A tile
            int r = l >> 5, c = l & 31;
            As[c][r] = Abase[r * FF + k0 + c];
            l += 256;
        }
        l = tid;
        #pragma unroll
        for (int it = 0; it < 8; it++) {   // 64x32 B tile
            int r = l >> 5, c = l & 31;
            Bs[c][r] = Bbase[r * FF + k0 + c];
            l += 256;
        }
        __syncthreads();
        #pragma unroll
        for (int kk = 0; kk < 32; kk++) {
            float2 a = *(const float2*)&As[kk][ty * 2];
            float4 b = *(const float4*)&Bs[kk][tx * 4];
            unsigned long long b01, b23, ad0, ad1;
            asm("mov.b64 %0, {%1, %2};" : "=l"(b01) : "f"(b.x), "f"(b.y));
            asm("mov.b64 %0, {%1, %2};" : "=l"(b23) : "f"(b.z), "f"(b.w));
            asm("mov.b64 %0, {%1, %1};" : "=l"(ad0) : "f"(a.x));
            asm("mov.b64 %0, {%1, %1};" : "=l"(ad1) : "f"(a.y));
            asm("fma.rn.f32x2 %0, %1, %2, %0;" : "+l"(acc00) : "l"(ad0), "l"(b01));
            asm("fma.rn.f32x2 %0, %1, %2, %0;" : "+l"(acc01) : "l"(ad0), "l"(b23));
            asm("fma.rn.f32x2 %0, %1, %2, %0;" : "+l"(acc10) : "l"(ad1), "l"(b01));
            asm("fma.rn.f32x2 %0, %1, %2, %0;" : "+l"(acc11) : "l"(ad1), "l"(b23));
        }
        __syncthreads();
    }
    // unpack + store
    float o0, o1, o2, o3;
    int r0 = row0 + ty * 2;
    int cbase = col0 + tx * 4;
    asm("mov.b64 {%0, %1}, %2;" : "=f"(o0), "=f"(o1) : "l"(acc00));
    asm("mov.b64 {%0, %1}, %2;" : "=f"(o2), "=f"(o3) : "l"(acc01));
    d_v[r0 * HH + cbase + 0] = o0;
    d_v[r0 * HH + cbase + 1] = o1;
    d_v[r0 * HH + cbase + 2] = o2;
    d_v[r0 * HH + cbase + 3] = o3;
    asm("mov.b64 {%0, %1}, %2;" : "=f"(o0), "=f"(o1) : "l"(acc10));
    asm("mov.b64 {%0, %1}, %2;" : "=f"(o2), "=f"(o3) : "l"(acc11));
    d_v[(r0 + 1) * HH + cbase + 0] = o0;
    d_v[(r0 + 1) * HH + cbase + 1] = o1;
    d_v[(r0 + 1) * HH + cbase + 2] = o2;
    d_v[(r0 + 1) * HH + cbase + 3] = o3;
}

// ------------- K7: h_s = leakyrelu(adj_s @ X0) (6 scenes) -------------
__global__ void k_h() {
    int s = blockIdx.x;   // 0..5
    int g = blockIdx.y;   // 0..15  (cols g*64 .. g*64+63)
    __shared__ float adjS[CC * CC];   // 25.6 KB
    __shared__ float xS[CC][64];      // 20.5 KB
    int tid = threadIdx.x;
    for (int i = tid; i < CC * CC; i += 256) adjS[i] = d_adj[s * CC * CC + i];
    for (int i = tid; i < CC * 64; i += 256) {
        int r = i >> 6, c = i & 63;
        xS[r][c] = d_X0[r * HH + g * 64 + c];
    }
    __syncthreads();
    int col = tid & 63;
    int r0 = tid >> 6;   // 0..3
    float acc[20];
    #pragma unroll
    for (int a = 0; a < 20; a++) acc[a] = 0.f;
    for (int k = 0; k < CC; k++) {
        float xv = xS[k][col];
        #pragma unroll
        for (int a = 0; a < 20; a++)
            acc[a] = fmaf(adjS[(r0 + 4 * a) * CC + k], xv, acc[a]);
    }
    #pragma unroll
    for (int a = 0; a < 20; a++) {
        int row = r0 + 4 * a;
        float hv = acc[a];
        hv = hv > 0.f ? hv : 0.2f * hv;
        d_hs[(s * CC + row) * HH + g * 64 + col] = hv;
    }
}

// ------------- K8: g = h_s · v[b];  output[b] = adj_s @ g -------------
__global__ void k_out(float* __restrict__ out) {
    int b = blockIdx.x;
    int tid = threadIdx.x;
    int lane = tid & 31, w = tid >> 5;
    __shared__ float vb[HH];
    __shared__ float g[CC];
    int s = d_ids[b];
    // vectorized copy of v[b] into smem
    ((float4*)vb)[tid] = ((const float4*)(d_v + (size_t)b * HH))[tid];
    __syncthreads();
    const float4* vb4 = (const float4*)vb;
    for (int j = w; j < CC; j += 8) {
        const float4* hr4 = (const float4*)(d_hs + (size_t)(s * CC + j) * HH);
        float acc = 0.f;
        #pragma unroll
        for (int k = 0; k < 8; k++) {
            float4 hv = hr4[lane + k * 32];
            float4 vv = vb4[lane + k * 32];
            acc = fmaf(hv.x, vv.x, acc);
            acc = fmaf(hv.y, vv.y, acc);
            acc = fmaf(hv.z, vv.z, acc);
            acc = fmaf(hv.w, vv.w, acc);
        }
        #pragma unroll
        for (int o = 16; o; o >>= 1) acc += __shfl_xor_sync(0xffffffffu, acc, o);
        if (lane == 0) g[j] = acc;
    }
    __syncthreads();
    if (tid < CC) {
        const float* ar = d_adj + s * CC * CC + tid * CC;
        float acc = 0.f;
        #pragma unroll 8
        for (int j = 0; j < CC; j++) acc = fmaf(ar[j], g[j], acc);
        out[OUT_OUTPUT + b * CC + tid] = acc;
    }
}

extern "C" void kernel_launch(void* const* d_in, const int* in_sizes, int n_in,
                              void* d_out, int out_size) {
    const float* x    = (const float*)d_in[0];
    const float* inp  = (const float*)d_in[1];
    const float* y    = (const float*)d_in[2];
    const float* com  = (const float*)d_in[3];
    const float* Wsc  = (const float*)d_in[4];
    const float* W1   = (const float*)d_in[5];
    const float* W2   = (const float*)d_in[6];
    float* out = (float*)d_out;

    // ---- fork point at capture start: x0 is input-only, overlaps maxpool ----
    cudaEventRecord(g_evStart, 0);
    cudaStreamWaitEvent(g_s2, g_evStart, 0);
    k_x0<<<dim3(8, 5), 256, 0, g_s2>>>(inp, W1);
    cudaEventRecord(g_evX0, g_s2);

    // ---- main stream ----
    k_maxpool<<<(BB * FF) / 8, 256>>>((const float4*)x);
    cudaEventRecord(g_evImg, 0);

    // side: vgemm after img ready (overlaps scene/comat/h)
    cudaStreamWaitEvent(g_s2, g_evImg, 0);
    k_vgemm<<<dim3(16, 8), 256, 0, g_s2>>>(W2);
    cudaEventRecord(g_evV, g_s2);

    // main continues
    k_scene<<<BB, 256>>>(Wsc, out);
    k_comat_adj<<<SS, 256>>>(y, com);
    cudaEventRecord(g_evAdj, 0);

    // side: gather (needs cp/ids/probs) overlaps h/out
    cudaStreamWaitEvent(g_s2, g_evAdj, 0);
    k_gather<<<3201, 256, 0, g_s2>>>(out);
    cudaEventRecord(g_evG, g_s2);

    // main: h needs X0 (side) + adj (main)
    cudaStreamWaitEvent(0, g_evX0, 0);
    k_h<<<dim3(6, 16), 256>>>();

    // main: out needs v (side) + hs/adj/ids (main)
    cudaStreamWaitEvent(0, g_evV, 0);
    k_out<<<BB, 256>>>(out);

    // join side stream before capture ends
    cudaStreamWaitEvent(0, g_evG, 0);
}